// round 7
// baseline (speedup 1.0000x reference)
#include <cuda_runtime.h>
#include <cstdint>

// Chamfer distance: B=8, N=M=4096, D=3 — bidirectional single-pass, round 7.
// R7 = R6 with pred split doubled (PC=32, grid 1024) to fix warp starvation
// (R6: 12 warps/SM, issue 49%).  Per-eval instruction cost unchanged.

constexpr int B       = 8;
constexpr int NPTS    = 4096;
constexpr int THREADS = 128;
constexpr int GPT     = 8;                       // resident gts per thread
constexpr int GTSB    = THREADS * GPT;           // 1024 gts per block
constexpr int GS      = NPTS / GTSB;             // 4 gt splits
constexpr int PCHUNK  = 128;                     // preds streamed per block
constexpr int PC      = NPTS / PCHUNK;           // 32 pred chunks
constexpr int NBLOCKS = B * PC * GS;             // 1024
constexpr int GRP     = 16;                      // preds per transpose group

__device__ float        g_colpart[B * PC * NPTS];  // [b][pc][gt] unclamped (4MB)
__device__ float        g_rowpart[B * GS * NPTS];  // [b][gs][pred] unclamped
__device__ float        g_batch[B];
__device__ unsigned int g_cnt_batch[B];
__device__ unsigned int g_cnt_final;

__device__ __forceinline__ uint64_t pack2(float lo, float hi) {
    uint64_t r; asm("mov.b64 %0, {%1,%2};" : "=l"(r) : "f"(lo), "f"(hi)); return r;
}
__device__ __forceinline__ uint64_t fma2(uint64_t a, uint64_t b, uint64_t c) {
    uint64_t d; asm("fma.rn.f32x2 %0, %1, %2, %3;" : "=l"(d) : "l"(a), "l"(b), "l"(c)); return d;
}
__device__ __forceinline__ uint64_t add2(uint64_t a, uint64_t b) {
    uint64_t d; asm("add.rn.f32x2 %0, %1, %2;" : "=l"(d) : "l"(a), "l"(b)); return d;
}
__device__ __forceinline__ void unpack2(uint64_t v, float& lo, float& hi) {
    asm("mov.b64 {%0,%1}, %2;" : "=f"(lo), "=f"(hi) : "l"(v));
}

__global__ __launch_bounds__(THREADS) void chamfer_bidir(
    const float* __restrict__ pred, const float* __restrict__ gt,
    float* __restrict__ out)
{
    __shared__ ulonglong2 sp[PCHUNK][2];      // {mxx,myy},{mzz,x2x2}  4KB
    __shared__ float      srow[PCHUNK][4];    // per-pred per-warp row mins 2KB
    __shared__ float      sred[4];
    __shared__ int        s_e1, s_e2;

    const int bx  = blockIdx.x;
    const int gs  = bx & (GS - 1);
    const int pc  = (bx >> 2) & (PC - 1);
    const int b   = bx >> 7;
    const int tid = threadIdx.x;
    const int wid = tid >> 5, lid = tid & 31;

    // ---- stage 128 preds (threads 0..63 stage 2 each), pre-packed ----
    if (tid < PCHUNK / 2) {
        const float2* pp = reinterpret_cast<const float2*>(
            pred + (size_t)b * NPTS * 3 + (size_t)pc * PCHUNK * 3);
        const float2 u0 = pp[3 * tid + 0];   // x0 y0
        const float2 u1 = pp[3 * tid + 1];   // z0 x1
        const float2 u2 = pp[3 * tid + 2];   // y1 z1
        const float x2a = fmaf(u0.x, u0.x, fmaf(u0.y, u0.y, u1.x * u1.x));
        const float x2b = fmaf(u1.y, u1.y, fmaf(u2.x, u2.x, u2.y * u2.y));
        sp[2 * tid + 0][0] = make_ulonglong2(pack2(-2.f * u0.x, -2.f * u0.x),
                                             pack2(-2.f * u0.y, -2.f * u0.y));
        sp[2 * tid + 0][1] = make_ulonglong2(pack2(-2.f * u1.x, -2.f * u1.x),
                                             pack2(x2a, x2a));
        sp[2 * tid + 1][0] = make_ulonglong2(pack2(-2.f * u1.y, -2.f * u1.y),
                                             pack2(-2.f * u2.x, -2.f * u2.x));
        sp[2 * tid + 1][1] = make_ulonglong2(pack2(-2.f * u2.y, -2.f * u2.y),
                                             pack2(x2b, x2b));
    }

    // ---- resident gt points: 4 packed pairs ----
    uint64_t gx[4], gy[4], gz[4], gw[4];
    {
        const float2* g = reinterpret_cast<const float2*>(
            gt + (size_t)b * NPTS * 3 + (size_t)(gs * GTSB + tid * GPT) * 3);
        #pragma unroll
        for (int q = 0; q < 4; ++q) {
            const float2 a = g[3 * q + 0];
            const float2 c = g[3 * q + 1];
            const float2 e = g[3 * q + 2];
            gx[q] = pack2(a.x, c.y);
            gy[q] = pack2(a.y, e.x);
            gz[q] = pack2(c.x, e.y);
            gw[q] = pack2(fmaf(a.x, a.x, fmaf(a.y, a.y, c.x * c.x)),
                          fmaf(c.y, c.y, fmaf(e.x, e.x, e.y * e.y)));
        }
    }
    __syncthreads();

    float cmin[GPT];
    #pragma unroll
    for (int i = 0; i < GPT; ++i) cmin[i] = 3.4e38f;

    // ---- main loop: 8 groups x 16 preds ----
    for (int grp = 0; grp < PCHUNK / GRP; ++grp) {
        float a[GRP];
        #pragma unroll
        for (int i = 0; i < GRP; ++i) {
            const int p = grp * GRP + i;
            const ulonglong2 A  = sp[p][0];
            const ulonglong2 Bv = sp[p][1];
            float m01[4];
            #pragma unroll
            for (int q = 0; q < 4; ++q) {
                uint64_t t = add2(gw[q], Bv.y);       // w + x2
                t = fma2(Bv.x, gz[q], t);
                t = fma2(A.y,  gy[q], t);
                t = fma2(A.x,  gx[q], t);
                float d0, d1;
                unpack2(t, d0, d1);
                cmin[2 * q + 0] = fminf(cmin[2 * q + 0], d0);
                cmin[2 * q + 1] = fminf(cmin[2 * q + 1], d1);
                m01[q] = fminf(d0, d1);
            }
            a[i] = fminf(fminf(m01[0], m01[1]), fminf(m01[2], m01[3]));
        }
        // Butterfly transpose-reduce: lane lid ends with warp-min for pred
        // grp*16 + (lid & 15).
        #pragma unroll
        for (int k = 1; k <= 8; k <<= 1) {
            const bool up = (lid & k) != 0;
            #pragma unroll
            for (int m = 0; m < GRP / (2 * k); ++m) {
                const float send = up ? a[2 * m] : a[2 * m + 1];
                const float t    = __shfl_xor_sync(0xffffffffu, send, k);
                a[m] = fminf(up ? a[2 * m + 1] : a[2 * m], t);
            }
        }
        a[0] = fminf(a[0], __shfl_xor_sync(0xffffffffu, a[0], 16));
        if (lid < GRP) srow[grp * GRP + lid][wid] = a[0];
    }
    __syncthreads();

    // ---- cross-warp row combine -> global row partials ----
    if (tid < PCHUNK) {
        const float4 v = *reinterpret_cast<const float4*>(srow[tid]);
        g_rowpart[(size_t)(b * GS + gs) * NPTS + pc * PCHUNK + tid] =
            fminf(fminf(v.x, v.y), fminf(v.z, v.w));
    }

    // ---- col partials -> global ----
    {
        float* cp = g_colpart + (size_t)(b * PC + pc) * NPTS + gs * GTSB + tid * GPT;
        reinterpret_cast<float4*>(cp)[0] = make_float4(cmin[0], cmin[1], cmin[2], cmin[3]);
        reinterpret_cast<float4*>(cp)[1] = make_float4(cmin[4], cmin[5], cmin[6], cmin[7]);
    }

    // ---- per-batch election (last of PC*GS = 128 blocks) ----
    __threadfence();
    if (tid == 0)
        s_e1 = (atomicAdd(&g_cnt_batch[b], 1u) == (unsigned)(PC * GS - 1));
    __syncthreads();
    if (!s_e1) return;
    __threadfence();

    {
        float sum = 0.0f;
        const float4* cpb = reinterpret_cast<const float4*>(g_colpart + (size_t)b * PC * NPTS);
        for (int g4 = tid; g4 < NPTS / 4; g4 += THREADS) {
            float4 m = __ldcg(&cpb[g4]);
            #pragma unroll 8
            for (int k = 1; k < PC; ++k) {
                const float4 v = __ldcg(&cpb[(size_t)k * (NPTS / 4) + g4]);
                m.x = fminf(m.x, v.x); m.y = fminf(m.y, v.y);
                m.z = fminf(m.z, v.z); m.w = fminf(m.w, v.w);
            }
            sum += fmaxf(m.x, 0.f) + fmaxf(m.y, 0.f) + fmaxf(m.z, 0.f) + fmaxf(m.w, 0.f);
        }
        const float4* rpb = reinterpret_cast<const float4*>(g_rowpart + (size_t)b * GS * NPTS);
        for (int p4 = tid; p4 < NPTS / 4; p4 += THREADS) {
            float4 m = __ldcg(&rpb[p4]);
            #pragma unroll
            for (int k = 1; k < GS; ++k) {
                const float4 v = __ldcg(&rpb[(size_t)k * (NPTS / 4) + p4]);
                m.x = fminf(m.x, v.x); m.y = fminf(m.y, v.y);
                m.z = fminf(m.z, v.z); m.w = fminf(m.w, v.w);
            }
            sum += fmaxf(m.x, 0.f) + fmaxf(m.y, 0.f) + fmaxf(m.z, 0.f) + fmaxf(m.w, 0.f);
        }
        #pragma unroll
        for (int off = 16; off; off >>= 1)
            sum += __shfl_down_sync(0xffffffffu, sum, off);
        if (lid == 0) sred[wid] = sum;
        __syncthreads();
        if (tid == 0)
            g_batch[b] = (sred[0] + sred[1]) + (sred[2] + sred[3]);
    }
    __syncthreads();

    // ---- global election (last of 8 batch leaders) ----
    __threadfence();
    if (tid == 0)
        s_e2 = (atomicAdd(&g_cnt_final, 1u) == (unsigned)(B - 1));
    __syncthreads();
    if (!s_e2) return;

    if (tid == 0) {
        __threadfence();
        float s = 0.0f;
        #pragma unroll
        for (int i = 0; i < B; ++i) s += __ldcg(&g_batch[i]);
        out[0] = s * (1.0f / (float)(B * NPTS));
        g_cnt_final = 0;
        #pragma unroll
        for (int i = 0; i < B; ++i) g_cnt_batch[i] = 0;
    }
}

extern "C" void kernel_launch(void* const* d_in, const int* in_sizes, int n_in,
                              void* d_out, int out_size)
{
    const float* pred = (const float*)d_in[0];
    const float* gt   = (const float*)d_in[1];
    float* out        = (float*)d_out;

    chamfer_bidir<<<NBLOCKS, THREADS>>>(pred, gt, out);
}

// round 8
// speedup vs baseline: 1.0382x; 1.0382x over previous
#include <cuda_runtime.h>
#include <cstdint>

// Chamfer distance: B=8, N=M=4096, D=3 — bidirectional single-pass, round 8.
// R8: one fully-resident wave. 1024 blocks x 128 thr, 8 blocks/SM (64-reg cap),
// 32 warps/SM to cover fma2 chain latency. GPT=4 resident gts, GRP=8 butterfly.

constexpr int B       = 8;
constexpr int NPTS    = 4096;
constexpr int THREADS = 128;
constexpr int GPT     = 4;                       // resident gts per thread
constexpr int GTSB    = THREADS * GPT;           // 512 gts per block
constexpr int GS      = NPTS / GTSB;             // 8 gt splits
constexpr int PCHUNK  = 256;                     // preds streamed per block
constexpr int PC      = NPTS / PCHUNK;           // 16 pred chunks
constexpr int NBLOCKS = B * PC * GS;             // 1024
constexpr int GRP     = 8;                       // preds per transpose group

__device__ float        g_colpart[B * PC * NPTS];  // [b][pc][gt] unclamped
__device__ float        g_rowpart[B * GS * NPTS];  // [b][gs][pred] unclamped
__device__ float        g_batch[B];
__device__ unsigned int g_cnt_batch[B];
__device__ unsigned int g_cnt_final;

__device__ __forceinline__ uint64_t pack2(float lo, float hi) {
    uint64_t r; asm("mov.b64 %0, {%1,%2};" : "=l"(r) : "f"(lo), "f"(hi)); return r;
}
__device__ __forceinline__ uint64_t fma2(uint64_t a, uint64_t b, uint64_t c) {
    uint64_t d; asm("fma.rn.f32x2 %0, %1, %2, %3;" : "=l"(d) : "l"(a), "l"(b), "l"(c)); return d;
}
__device__ __forceinline__ uint64_t add2(uint64_t a, uint64_t b) {
    uint64_t d; asm("add.rn.f32x2 %0, %1, %2;" : "=l"(d) : "l"(a), "l"(b)); return d;
}
__device__ __forceinline__ void unpack2(uint64_t v, float& lo, float& hi) {
    asm("mov.b64 {%0,%1}, %2;" : "=f"(lo), "=f"(hi) : "l"(v));
}

__global__ __launch_bounds__(THREADS, 8) void chamfer_bidir(
    const float* __restrict__ pred, const float* __restrict__ gt,
    float* __restrict__ out)
{
    __shared__ ulonglong2 sp[PCHUNK][2];      // {mxx,myy},{mzz,x2x2}  8KB
    __shared__ float      srow[PCHUNK][4];    // per-pred per-warp row mins 4KB
    __shared__ float      sred[4];
    __shared__ int        s_e1, s_e2;

    const int bx  = blockIdx.x;
    const int gs  = bx & (GS - 1);
    const int pc  = (bx >> 3) & (PC - 1);
    const int b   = bx >> 7;
    const int tid = threadIdx.x;
    const int wid = tid >> 5, lid = tid & 31;

    // ---- stage 256 preds (2 per thread), pre-packed ----
    {
        const float2* pp = reinterpret_cast<const float2*>(
            pred + (size_t)b * NPTS * 3 + (size_t)pc * PCHUNK * 3);
        const float2 u0 = pp[3 * tid + 0];   // x0 y0
        const float2 u1 = pp[3 * tid + 1];   // z0 x1
        const float2 u2 = pp[3 * tid + 2];   // y1 z1
        const float x2a = fmaf(u0.x, u0.x, fmaf(u0.y, u0.y, u1.x * u1.x));
        const float x2b = fmaf(u1.y, u1.y, fmaf(u2.x, u2.x, u2.y * u2.y));
        sp[2 * tid + 0][0] = make_ulonglong2(pack2(-2.f * u0.x, -2.f * u0.x),
                                             pack2(-2.f * u0.y, -2.f * u0.y));
        sp[2 * tid + 0][1] = make_ulonglong2(pack2(-2.f * u1.x, -2.f * u1.x),
                                             pack2(x2a, x2a));
        sp[2 * tid + 1][0] = make_ulonglong2(pack2(-2.f * u1.y, -2.f * u1.y),
                                             pack2(-2.f * u2.x, -2.f * u2.x));
        sp[2 * tid + 1][1] = make_ulonglong2(pack2(-2.f * u2.y, -2.f * u2.y),
                                             pack2(x2b, x2b));
    }

    // ---- resident gt points: 2 packed pairs (GPT=4) ----
    uint64_t gx[2], gy[2], gz[2], gw[2];
    {
        const float2* g = reinterpret_cast<const float2*>(
            gt + (size_t)b * NPTS * 3 + (size_t)(gs * GTSB + tid * GPT) * 3);
        #pragma unroll
        for (int q = 0; q < 2; ++q) {
            const float2 a = g[3 * q + 0];
            const float2 c = g[3 * q + 1];
            const float2 e = g[3 * q + 2];
            gx[q] = pack2(a.x, c.y);
            gy[q] = pack2(a.y, e.x);
            gz[q] = pack2(c.x, e.y);
            gw[q] = pack2(fmaf(a.x, a.x, fmaf(a.y, a.y, c.x * c.x)),
                          fmaf(c.y, c.y, fmaf(e.x, e.x, e.y * e.y)));
        }
    }
    __syncthreads();

    float cmin[GPT];
    #pragma unroll
    for (int i = 0; i < GPT; ++i) cmin[i] = 3.4e38f;

    // ---- main loop: 32 groups x 8 preds ----
    for (int grp = 0; grp < PCHUNK / GRP; ++grp) {
        float a[GRP];
        #pragma unroll
        for (int i = 0; i < GRP; ++i) {
            const int p = grp * GRP + i;
            const ulonglong2 A  = sp[p][0];
            const ulonglong2 Bv = sp[p][1];
            float m01[2];
            #pragma unroll
            for (int q = 0; q < 2; ++q) {
                uint64_t t = add2(gw[q], Bv.y);       // w + x2
                t = fma2(Bv.x, gz[q], t);
                t = fma2(A.y,  gy[q], t);
                t = fma2(A.x,  gx[q], t);
                float d0, d1;
                unpack2(t, d0, d1);
                cmin[2 * q + 0] = fminf(cmin[2 * q + 0], d0);
                cmin[2 * q + 1] = fminf(cmin[2 * q + 1], d1);
                m01[q] = fminf(d0, d1);
            }
            a[i] = fminf(m01[0], m01[1]);
        }
        // Butterfly transpose-reduce over the 8-element register array:
        // after k=1,2,4 lane lid holds (partial) min for pred grp*8+(lid&7);
        // k=8,16 fold the 4 replicated lane groups.
        #pragma unroll
        for (int k = 1; k <= 4; k <<= 1) {
            const bool up = (lid & k) != 0;
            #pragma unroll
            for (int m = 0; m < GRP / (2 * k); ++m) {
                const float send = up ? a[2 * m] : a[2 * m + 1];
                const float t    = __shfl_xor_sync(0xffffffffu, send, k);
                a[m] = fminf(up ? a[2 * m + 1] : a[2 * m], t);
            }
        }
        a[0] = fminf(a[0], __shfl_xor_sync(0xffffffffu, a[0], 8));
        a[0] = fminf(a[0], __shfl_xor_sync(0xffffffffu, a[0], 16));
        if (lid < GRP) srow[grp * GRP + lid][wid] = a[0];
    }
    __syncthreads();

    // ---- cross-warp row combine -> global row partials ----
    #pragma unroll
    for (int p = tid; p < PCHUNK; p += THREADS) {
        const float4 v = *reinterpret_cast<const float4*>(srow[p]);
        g_rowpart[(size_t)(b * GS + gs) * NPTS + pc * PCHUNK + p] =
            fminf(fminf(v.x, v.y), fminf(v.z, v.w));
    }

    // ---- col partials -> global ----
    g_colpart[0] = g_colpart[0];  // no-op keep symbol
    {
        float* cp = g_colpart + (size_t)(b * PC + pc) * NPTS + gs * GTSB + tid * GPT;
        *reinterpret_cast<float4*>(cp) = make_float4(cmin[0], cmin[1], cmin[2], cmin[3]);
    }

    // ---- per-batch election (last of PC*GS = 128 blocks) ----
    __threadfence();
    if (tid == 0)
        s_e1 = (atomicAdd(&g_cnt_batch[b], 1u) == (unsigned)(PC * GS - 1));
    __syncthreads();
    if (!s_e1) return;
    __threadfence();

    {
        float sum = 0.0f;
        const float4* cpb = reinterpret_cast<const float4*>(g_colpart + (size_t)b * PC * NPTS);
        for (int g4 = tid; g4 < NPTS / 4; g4 += THREADS) {
            float4 m = __ldcg(&cpb[g4]);
            #pragma unroll
            for (int k = 1; k < PC; ++k) {
                const float4 v = __ldcg(&cpb[(size_t)k * (NPTS / 4) + g4]);
                m.x = fminf(m.x, v.x); m.y = fminf(m.y, v.y);
                m.z = fminf(m.z, v.z); m.w = fminf(m.w, v.w);
            }
            sum += fmaxf(m.x, 0.f) + fmaxf(m.y, 0.f) + fmaxf(m.z, 0.f) + fmaxf(m.w, 0.f);
        }
        const float4* rpb = reinterpret_cast<const float4*>(g_rowpart + (size_t)b * GS * NPTS);
        for (int p4 = tid; p4 < NPTS / 4; p4 += THREADS) {
            float4 m = __ldcg(&rpb[p4]);
            #pragma unroll
            for (int k = 1; k < GS; ++k) {
                const float4 v = __ldcg(&rpb[(size_t)k * (NPTS / 4) + p4]);
                m.x = fminf(m.x, v.x); m.y = fminf(m.y, v.y);
                m.z = fminf(m.z, v.z); m.w = fminf(m.w, v.w);
            }
            sum += fmaxf(m.x, 0.f) + fmaxf(m.y, 0.f) + fmaxf(m.z, 0.f) + fmaxf(m.w, 0.f);
        }
        #pragma unroll
        for (int off = 16; off; off >>= 1)
            sum += __shfl_down_sync(0xffffffffu, sum, off);
        if (lid == 0) sred[wid] = sum;
        __syncthreads();
        if (tid == 0)
            g_batch[b] = (sred[0] + sred[1]) + (sred[2] + sred[3]);
    }
    __syncthreads();

    // ---- global election (last of 8 batch leaders) ----
    __threadfence();
    if (tid == 0)
        s_e2 = (atomicAdd(&g_cnt_final, 1u) == (unsigned)(B - 1));
    __syncthreads();
    if (!s_e2) return;

    if (tid == 0) {
        __threadfence();
        float s = 0.0f;
        #pragma unroll
        for (int i = 0; i < B; ++i) s += __ldcg(&g_batch[i]);
        out[0] = s * (1.0f / (float)(B * NPTS));
        g_cnt_final = 0;
        #pragma unroll
        for (int i = 0; i < B; ++i) g_cnt_batch[i] = 0;
    }
}

extern "C" void kernel_launch(void* const* d_in, const int* in_sizes, int n_in,
                              void* d_out, int out_size)
{
    const float* pred = (const float*)d_in[0];
    const float* gt   = (const float*)d_in[1];
    float* out        = (float*)d_out;

    chamfer_bidir<<<NBLOCKS, THREADS>>>(pred, gt, out);
}